// round 3
// baseline (speedup 1.0000x reference)
#include <cuda_runtime.h>
#include <cstdint>

#define NROW 8192

// ---------------- scratch (static __device__, no allocs) ----------------
__device__ float g_Wm [NROW*64];
__device__ float g_Wv [NROW*96];
__device__ float g_XFm[NROW*64];
__device__ float g_XFv[NROW*96];
__device__ float g_Lm [NROW*32];
__device__ float g_Lv [NROW*32];
__device__ float g_QNm[NROW];
__device__ float g_QNv[NROW];
__device__ float g_XNm[NROW];
__device__ float g_XNv[NROW];
__device__ float g_Zm [NROW*32];
__device__ float g_Zv [NROW*32];

__device__ __forceinline__ unsigned f2tf(float x){
  unsigned r; asm("cvt.rna.tf32.f32 %0, %1;" : "=r"(r) : "f"(x)); return r;
}
__device__ __forceinline__ float tf2f(float x){ return __uint_as_float(f2tf(x)); }
__device__ __forceinline__ float ex2f(float x){
  float r; asm("ex2.approx.f32 %0, %1;" : "=f"(r) : "f"(x)); return r;
}
__device__ __forceinline__ unsigned fbits(float x){ return __float_as_uint(x); }
__device__ __forceinline__ float4 cvt4(float4 v){
  v.x=tf2f(v.x); v.y=tf2f(v.y); v.z=tf2f(v.z); v.w=tf2f(v.w); return v;
}
__device__ __forceinline__ void mma8(float* c, unsigned a0,unsigned a1,unsigned a2,unsigned a3,
                                     unsigned b0,unsigned b1){
  asm volatile("mma.sync.aligned.m16n8k8.row.col.f32.tf32.tf32.f32 "
               "{%0,%1,%2,%3},{%4,%5,%6,%7},{%8,%9},{%0,%1,%2,%3};\n"
               : "+f"(c[0]), "+f"(c[1]), "+f"(c[2]), "+f"(c[3])
               : "r"(a0), "r"(a1), "r"(a2), "r"(a3), "r"(b0), "r"(b1));
}

// ---------------- 1) prep ----------------
__global__ __launch_bounds__(256) void prep_kernel(
    const float* __restrict__ x_mu, const float* __restrict__ y_eta,
    const float* __restrict__ y_mean, const float* __restrict__ y_var,
    const float* __restrict__ X_mean, const float* __restrict__ X_var){
  int row  = blockIdx.x*8 + (threadIdx.x>>5);
  int lane = threadIdx.x & 31;
  float xm = x_mu [row*32+lane];
  float s  = y_mean[row*32+lane] + y_var[row*32+lane];
  float fe = 0.01f * y_eta[(NROW-1-row)*32+lane];
  g_Wm[row*64+lane]    = tf2f(xm);
  g_Wm[row*64+32+lane] = tf2f(s);
  g_Wv[row*96+lane]    = tf2f(xm);
  g_Wv[row*96+32+lane] = tf2f(fe);
  g_Wv[row*96+64+lane] = tf2f(s);
  float qm = xm*xm + s*s;
  float qv = qm + fe*fe;
  float a  = X_mean[row*64+lane], bm = X_mean[row*64+32+lane];
  g_XFm[row*64+lane]    = tf2f(a);
  g_XFm[row*64+32+lane] = tf2f(bm);
  float nm = a*a + bm*bm;
  float c0 = X_var[row*96+lane], c1 = X_var[row*96+32+lane], c2 = X_var[row*96+64+lane];
  g_XFv[row*96+lane]    = tf2f(c0);
  g_XFv[row*96+32+lane] = tf2f(c1);
  g_XFv[row*96+64+lane] = tf2f(c2);
  float nv = c0*c0 + c1*c1 + c2*c2;
  #pragma unroll
  for(int o=16;o;o>>=1){
    qm += __shfl_xor_sync(0xffffffffu,qm,o);
    qv += __shfl_xor_sync(0xffffffffu,qv,o);
    nm += __shfl_xor_sync(0xffffffffu,nm,o);
    nv += __shfl_xor_sync(0xffffffffu,nv,o);
  }
  if(lane==0){ g_QNm[row]=qm; g_QNv[row]=qv; g_XNm[row]=nm; g_XNv[row]=nv; }
}

// ---------------- 2) Lambda = kXXinv @ Z ----------------
// BM=32, 64 threads, grid (256,2). LDG of next tile overlapped with mma.
__global__ __launch_bounds__(64) void lambda_kernel(
    const float* __restrict__ Am, const float* __restrict__ Av,
    const float* __restrict__ Zm, const float* __restrict__ Zv){
  const float *A, *Z; float* L;
  if(blockIdx.y==0){ A=Am; Z=Zm; L=g_Lm; } else { A=Av; Z=Zv; L=g_Lv; }
  __shared__ float As[32*36];
  __shared__ float Zs[32*40];
  int tid=threadIdx.x, w=tid>>5, lane=tid&31, gr=lane>>2, p=lane&3;
  int rb = blockIdx.x*32;
  float4 ra[4], rz[4];
  #pragma unroll
  for(int i=0;i<4;i++){
    int idx=tid+64*i; int r=idx>>3, c4=idx&7;
    ra[i]=*(const float4*)&A[(size_t)(rb+r)*NROW + c4*4];
    rz[i]=*(const float4*)&Z[r*32 + c4*4];
  }
  float acc[16];
  #pragma unroll
  for(int i=0;i<16;i++) acc[i]=0.f;
  for(int kt=0;kt<NROW/32;kt++){
    #pragma unroll
    for(int i=0;i<4;i++){
      int idx=tid+64*i; int r=idx>>3, c4=idx&7;
      *(float4*)&As[r*36+c4*4]=cvt4(ra[i]);
      *(float4*)&Zs[r*40+c4*4]=cvt4(rz[i]);
    }
    __syncthreads();
    if(kt<NROW/32-1){
      int k0=(kt+1)*32;
      #pragma unroll
      for(int i=0;i<4;i++){
        int idx=tid+64*i; int r=idx>>3, c4=idx&7;
        ra[i]=*(const float4*)&A[(size_t)(rb+r)*NROW + k0 + c4*4];
        rz[i]=*(const float4*)&Z[(k0+r)*32 + c4*4];
      }
    }
    #pragma unroll
    for(int kc=0;kc<4;kc++){
      unsigned a0=fbits(As[(w*16+gr  )*36 + kc*8+p  ]);
      unsigned a1=fbits(As[(w*16+gr+8)*36 + kc*8+p  ]);
      unsigned a2=fbits(As[(w*16+gr  )*36 + kc*8+p+4]);
      unsigned a3=fbits(As[(w*16+gr+8)*36 + kc*8+p+4]);
      #pragma unroll
      for(int nt=0;nt<4;nt++){
        unsigned b0=fbits(Zs[(kc*8+p  )*40 + nt*8+gr]);
        unsigned b1=fbits(Zs[(kc*8+p+4)*40 + nt*8+gr]);
        mma8(&acc[nt*4], a0,a1,a2,a3, b0,b1);
      }
    }
    __syncthreads();
  }
  int q = rb + w*16 + gr;
  #pragma unroll
  for(int nt=0;nt<4;nt++){
    L[ q   *32 + nt*8 + 2*p  ] = tf2f(acc[nt*4+0]);
    L[ q   *32 + nt*8 + 2*p+1] = tf2f(acc[nt*4+1]);
    L[(q+8)*32 + nt*8 + 2*p  ] = tf2f(acc[nt*4+2]);
    L[(q+8)*32 + nt*8 + 2*p+1] = tf2f(acc[nt*4+3]);
  }
}

// ---------------- 3) fused scores -> exp -> PV ----------------
template<int D>
__device__ __forceinline__ void fused_body(
    const float* __restrict__ Wf, const float* __restrict__ XF,
    const float* __restrict__ Lam, const float* __restrict__ QN,
    const float* __restrict__ XN, float* __restrict__ Zout, int qblk){
  extern __shared__ float sm[];
  const int SD = D + 4;
  float* Xs  = sm;                  // 128*SD
  float* Ls  = sm + 128*SD;         // 128*40
  float* xns = Ls + 128*40;         // 128
  float* Kt  = xns + 128;           // 8 * 16*36 (per-warp staging)
  int tid=threadIdx.x, w=tid>>5, lane=tid&31, gr=lane>>2, p=lane&3;
  float* Kw = Kt + w*16*36;
  int q0 = qblk*128;
  const int NF4 = 128*(D/4);
  // stage W tile through Xs, extract A-frags into registers
  for(int i=tid;i<NF4;i+=256){
    int r=i/(D/4), c4=i%(D/4);
    *(float4*)&Xs[r*SD+c4*4] = *(const float4*)&Wf[(q0+r)*D + c4*4];
  }
  __syncthreads();
  unsigned wa[D/8][4];
  #pragma unroll
  for(int kk=0;kk<D/8;kk++){
    wa[kk][0]=fbits(Xs[(w*16+gr  )*SD + kk*8+p  ]);
    wa[kk][1]=fbits(Xs[(w*16+gr+8)*SD + kk*8+p  ]);
    wa[kk][2]=fbits(Xs[(w*16+gr  )*SD + kk*8+p+4]);
    wa[kk][3]=fbits(Xs[(w*16+gr+8)*SD + kk*8+p+4]);
  }
  float qn0 = QN[q0+w*16+gr];
  float qn1 = QN[q0+w*16+gr+8];
  __syncthreads();
  float z[16];
  #pragma unroll
  for(int i=0;i<16;i++) z[i]=0.f;
  const float CL = 1.1271055e-2f;   // log2(e)/128
  for(int xb=0;xb<NROW;xb+=128){
    for(int i=tid;i<NF4;i+=256){
      int r=i/(D/4), c4=i%(D/4);
      *(float4*)&Xs[r*SD+c4*4] = *(const float4*)&XF[(xb+r)*D + c4*4];
    }
    for(int i=tid;i<1024;i+=256){
      int r=i>>3, c4=i&7;
      *(float4*)&Ls[r*40+c4*4] = *(const float4*)&Lam[(xb+r)*32 + c4*4];
    }
    if(tid<128) xns[tid]=XN[xb+tid];
    __syncthreads();
    #pragma unroll
    for(int xs=0;xs<4;xs++){
      float s[16];
      #pragma unroll
      for(int i=0;i<16;i++) s[i]=0.f;
      #pragma unroll
      for(int kk=0;kk<D/8;kk++){
        #pragma unroll
        for(int nt=0;nt<4;nt++){
          unsigned b0=fbits(Xs[(xs*32+nt*8+gr)*SD + kk*8+p  ]);
          unsigned b1=fbits(Xs[(xs*32+nt*8+gr)*SD + kk*8+p+4]);
          mma8(&s[nt*4], wa[kk][0],wa[kk][1],wa[kk][2],wa[kk][3], b0,b1);
        }
      }
      #pragma unroll
      for(int nt=0;nt<4;nt++){
        float xnA=xns[xs*32+nt*8+2*p], xnB=xns[xs*32+nt*8+2*p+1];
        Kw[ gr   *36+nt*8+2*p  ]=tf2f(ex2f(fminf(2.f*s[nt*4+0]-qn0-xnA,0.f)*CL));
        Kw[ gr   *36+nt*8+2*p+1]=tf2f(ex2f(fminf(2.f*s[nt*4+1]-qn0-xnB,0.f)*CL));
        Kw[(gr+8)*36+nt*8+2*p  ]=tf2f(ex2f(fminf(2.f*s[nt*4+2]-qn1-xnA,0.f)*CL));
        Kw[(gr+8)*36+nt*8+2*p+1]=tf2f(ex2f(fminf(2.f*s[nt*4+3]-qn1-xnB,0.f)*CL));
      }
      __syncwarp();
      #pragma unroll
      for(int kc=0;kc<4;kc++){
        unsigned a0=fbits(Kw[ gr   *36+kc*8+p  ]);
        unsigned a1=fbits(Kw[(gr+8)*36+kc*8+p  ]);
        unsigned a2=fbits(Kw[ gr   *36+kc*8+p+4]);
        unsigned a3=fbits(Kw[(gr+8)*36+kc*8+p+4]);
        #pragma unroll
        for(int nt=0;nt<4;nt++){
          unsigned b0=fbits(Ls[(xs*32+kc*8+p  )*40 + nt*8+gr]);
          unsigned b1=fbits(Ls[(xs*32+kc*8+p+4)*40 + nt*8+gr]);
          mma8(&z[nt*4], a0,a1,a2,a3, b0,b1);
        }
      }
      __syncwarp();
    }
    __syncthreads();
  }
  int q = q0 + w*16 + gr;
  #pragma unroll
  for(int nt=0;nt<4;nt++){
    Zout[ q   *32 + nt*8 + 2*p  ] = z[nt*4+0];
    Zout[ q   *32 + nt*8 + 2*p+1] = z[nt*4+1];
    Zout[(q+8)*32 + nt*8 + 2*p  ] = z[nt*4+2];
    Zout[(q+8)*32 + nt*8 + 2*p+1] = z[nt*4+3];
  }
}

__global__ __launch_bounds__(256) void fused_kernel(){
  if(blockIdx.y==0) fused_body<64>(g_Wm,g_XFm,g_Lm,g_QNm,g_XNm,g_Zm,blockIdx.x);
  else              fused_body<96>(g_Wv,g_XFv,g_Lv,g_QNv,g_XNv,g_Zv,blockIdx.x);
}

// ---------------- 4) finalize ----------------
__global__ __launch_bounds__(256) void final_kernel(
    const float* __restrict__ y_mean, const float* __restrict__ y_var,
    float* __restrict__ out){
  int i = blockIdx.x*256 + threadIdx.x;   // float4 index, 65536 total
  float4 a=*(const float4*)&y_mean[i*4];
  float4 b=*(const float4*)&y_var [i*4];
  float4 zm=*(const float4*)&g_Zm[i*4];
  float4 zv=*(const float4*)&g_Zv[i*4];
  float4 o;
  o.x=a.x+b.x+zm.x+zv.x; o.y=a.y+b.y+zm.y+zv.y;
  o.z=a.z+b.z+zm.z+zv.z; o.w=a.w+b.w+zm.w+zv.w;
  *(float4*)&out[i*4]=o;
}

extern "C" void kernel_launch(void* const* d_in, const int* in_sizes, int n_in,
                              void* d_out, int out_size){
  const float* x_mu   = (const float*)d_in[0];
  const float* y_eta  = (const float*)d_in[1];
  const float* y_mean = (const float*)d_in[2];
  const float* y_var  = (const float*)d_in[3];
  const float* X_mean = (const float*)d_in[4];
  const float* X_var  = (const float*)d_in[5];
  const float* Z_mean = (const float*)d_in[6];
  const float* Z_var  = (const float*)d_in[7];
  const float* kMinv  = (const float*)d_in[8];
  const float* kVinv  = (const float*)d_in[9];
  float* out = (float*)d_out;

  prep_kernel<<<NROW/8, 256>>>(x_mu, y_eta, y_mean, y_var, X_mean, X_var);
  lambda_kernel<<<dim3(NROW/32,2), 64>>>(kMinv, kVinv, Z_mean, Z_var);
  const int FSM = (128*100 + 128*40 + 128 + 8*16*36)*4;   // 90624 B
  cudaFuncSetAttribute(fused_kernel, cudaFuncAttributeMaxDynamicSharedMemorySize, FSM);
  fused_kernel<<<dim3(64,2), 256, FSM>>>();
  final_kernel<<<NROW*32/4/256, 256>>>(y_mean, y_var, out);
}

// round 4
// speedup vs baseline: 1.7744x; 1.7744x over previous
#include <cuda_runtime.h>
#include <cstdint>

#define NROW 8192

// ---------------- scratch ----------------
__device__ float g_Wm [NROW*64];         // pair-interleaved cols
__device__ float g_Wv [NROW*96];
__device__ float g_XFm[NROW*64];
__device__ float g_XFv[NROW*96];
__device__ float g_Lp [2][4][NROW*32];   // lambda partials (fp32)
__device__ float g_LTm[32*NROW];         // Lambda^T, row-interleaved, tf32
__device__ float g_LTv[32*NROW];
__device__ float g_QNm[NROW];
__device__ float g_QNv[NROW];
__device__ float g_XNm[NROW];
__device__ float g_XNv[NROW];
__device__ float g_Zm [NROW*32];
__device__ float g_Zv [NROW*32];

__device__ __forceinline__ unsigned f2tf(float x){
  unsigned r; asm("cvt.rna.tf32.f32 %0, %1;" : "=r"(r) : "f"(x)); return r;
}
__device__ __forceinline__ float tf2f(float x){ return __uint_as_float(f2tf(x)); }
__device__ __forceinline__ float ex2f(float x){
  float r; asm("ex2.approx.f32 %0, %1;" : "=f"(r) : "f"(x)); return r;
}
__device__ __forceinline__ unsigned fbits(float x){ return __float_as_uint(x); }
__device__ __forceinline__ float4 cvt4(float4 v){
  v.x=tf2f(v.x); v.y=tf2f(v.y); v.z=tf2f(v.z); v.w=tf2f(v.w); return v;
}
__device__ __forceinline__ void mma8(float* c, unsigned a0,unsigned a1,unsigned a2,unsigned a3,
                                     unsigned b0,unsigned b1){
  asm volatile("mma.sync.aligned.m16n8k8.row.col.f32.tf32.tf32.f32 "
               "{%0,%1,%2,%3},{%4,%5,%6,%7},{%8,%9},{%0,%1,%2,%3};\n"
               : "+f"(c[0]), "+f"(c[1]), "+f"(c[2]), "+f"(c[3])
               : "r"(a0), "r"(a1), "r"(a2), "r"(a3), "r"(b0), "r"(b1));
}
__device__ __forceinline__ void cpa16(void* dst, const void* src){
  unsigned d = (unsigned)__cvta_generic_to_shared(dst);
  asm volatile("cp.async.cg.shared.global [%0], [%1], 16;\n" :: "r"(d), "l"(src));
}
__device__ __forceinline__ void cpa_commit(){ asm volatile("cp.async.commit_group;\n"); }
__device__ __forceinline__ void cpa_wait0(){ asm volatile("cp.async.wait_group 0;\n"); }

// pair-interleave within 8-groups: orig offset j -> 2*(j&3) + ((j&4)>>2)
__device__ __forceinline__ int ilv(int j){ return (j & ~7) + 2*(j&3) + ((j&4)>>2); }

// ---------------- 1) prep (writes interleaved features) ----------------
__global__ __launch_bounds__(256) void prep_kernel(
    const float* __restrict__ x_mu, const float* __restrict__ y_eta,
    const float* __restrict__ y_mean, const float* __restrict__ y_var,
    const float* __restrict__ X_mean, const float* __restrict__ X_var){
  int row  = blockIdx.x*8 + (threadIdx.x>>5);
  int lane = threadIdx.x & 31;
  int il   = ilv(lane);
  float xm = x_mu [row*32+lane];
  float s  = y_mean[row*32+lane] + y_var[row*32+lane];
  float fe = 0.01f * y_eta[(NROW-1-row)*32+lane];
  g_Wm[row*64+il]    = tf2f(xm);
  g_Wm[row*64+32+il] = tf2f(s);
  g_Wv[row*96+il]    = tf2f(xm);
  g_Wv[row*96+32+il] = tf2f(fe);
  g_Wv[row*96+64+il] = tf2f(s);
  float qm = xm*xm + s*s;
  float qv = qm + fe*fe;
  float a  = X_mean[row*64+lane], bm = X_mean[row*64+32+lane];
  g_XFm[row*64+il]    = tf2f(a);
  g_XFm[row*64+32+il] = tf2f(bm);
  float nm = a*a + bm*bm;
  float c0 = X_var[row*96+lane], c1 = X_var[row*96+32+lane], c2 = X_var[row*96+64+lane];
  g_XFv[row*96+il]    = tf2f(c0);
  g_XFv[row*96+32+il] = tf2f(c1);
  g_XFv[row*96+64+il] = tf2f(c2);
  float nv = c0*c0 + c1*c1 + c2*c2;
  #pragma unroll
  for(int o=16;o;o>>=1){
    qm += __shfl_xor_sync(0xffffffffu,qm,o);
    qv += __shfl_xor_sync(0xffffffffu,qv,o);
    nm += __shfl_xor_sync(0xffffffffu,nm,o);
    nv += __shfl_xor_sync(0xffffffffu,nv,o);
  }
  if(lane==0){ g_QNm[row]=qm; g_QNv[row]=qv; g_XNm[row]=nm; g_XNv[row]=nv; }
}

// ---------------- 2) Lambda partials (K-split x4) ----------------
__global__ __launch_bounds__(64) void lambda_kernel(
    const float* __restrict__ Am, const float* __restrict__ Av,
    const float* __restrict__ Zm, const float* __restrict__ Zv){
  int path = blockIdx.z, ks = blockIdx.y;
  const float* A = path ? Av : Am;
  const float* Z = path ? Zv : Zm;
  float* L = &g_Lp[path][ks][0];
  __shared__ float As[32*36];
  __shared__ float Zs[32*40];
  int tid=threadIdx.x, w=tid>>5, lane=tid&31, gr=lane>>2, p=lane&3;
  int rb = blockIdx.x*32, kbase = ks*2048;
  float4 ra[4], rz[4];
  #pragma unroll
  for(int i=0;i<4;i++){
    int idx=tid+64*i; int r=idx>>3, c4=idx&7;
    ra[i]=*(const float4*)&A[(size_t)(rb+r)*NROW + kbase + c4*4];
    rz[i]=*(const float4*)&Z[(kbase+r)*32 + c4*4];
  }
  float acc[16];
  #pragma unroll
  for(int i=0;i<16;i++) acc[i]=0.f;
  for(int kt=0;kt<64;kt++){
    #pragma unroll
    for(int i=0;i<4;i++){
      int idx=tid+64*i; int r=idx>>3, c4=idx&7;
      *(float4*)&As[r*36+c4*4]=cvt4(ra[i]);
      *(float4*)&Zs[r*40+c4*4]=cvt4(rz[i]);
    }
    __syncthreads();
    if(kt<63){
      int k0=kbase+(kt+1)*32;
      #pragma unroll
      for(int i=0;i<4;i++){
        int idx=tid+64*i; int r=idx>>3, c4=idx&7;
        ra[i]=*(const float4*)&A[(size_t)(rb+r)*NROW + k0 + c4*4];
        rz[i]=*(const float4*)&Z[(k0+r)*32 + c4*4];
      }
    }
    #pragma unroll
    for(int kc=0;kc<4;kc++){
      unsigned a0=fbits(As[(w*16+gr  )*36 + kc*8+p  ]);
      unsigned a1=fbits(As[(w*16+gr+8)*36 + kc*8+p  ]);
      unsigned a2=fbits(As[(w*16+gr  )*36 + kc*8+p+4]);
      unsigned a3=fbits(As[(w*16+gr+8)*36 + kc*8+p+4]);
      #pragma unroll
      for(int nt=0;nt<4;nt++){
        unsigned b0=fbits(Zs[(kc*8+p  )*40 + nt*8+gr]);
        unsigned b1=fbits(Zs[(kc*8+p+4)*40 + nt*8+gr]);
        mma8(&acc[nt*4], a0,a1,a2,a3, b0,b1);
      }
    }
    __syncthreads();
  }
  int q = rb + w*16 + gr;
  #pragma unroll
  for(int nt=0;nt<4;nt++){
    L[ q   *32 + nt*8 + 2*p  ] = acc[nt*4+0];
    L[ q   *32 + nt*8 + 2*p+1] = acc[nt*4+1];
    L[(q+8)*32 + nt*8 + 2*p  ] = acc[nt*4+2];
    L[(q+8)*32 + nt*8 + 2*p+1] = acc[nt*4+3];
  }
}

// ---------------- 2b) reduce partials -> Lambda^T interleaved ----------------
__global__ __launch_bounds__(256) void reduce_kernel(){
  int path = blockIdx.y;
  int idx  = blockIdx.x*256 + threadIdx.x;   // 65536 float4 per path
  int r = idx>>3, c4 = idx&7;
  float4 s0 = *(const float4*)&g_Lp[path][0][idx*4];
  float4 s1 = *(const float4*)&g_Lp[path][1][idx*4];
  float4 s2 = *(const float4*)&g_Lp[path][2][idx*4];
  float4 s3 = *(const float4*)&g_Lp[path][3][idx*4];
  float vx = s0.x+s1.x+s2.x+s3.x;
  float vy = s0.y+s1.y+s2.y+s3.y;
  float vz = s0.z+s1.z+s2.z+s3.z;
  float vw = s0.w+s1.w+s2.w+s3.w;
  int pos = ilv(r);
  float* LT = path ? g_LTv : g_LTm;
  LT[(c4*4+0)*NROW + pos] = tf2f(vx);
  LT[(c4*4+1)*NROW + pos] = tf2f(vy);
  LT[(c4*4+2)*NROW + pos] = tf2f(vz);
  LT[(c4*4+3)*NROW + pos] = tf2f(vw);
}

// ---------------- 3) fused scores -> exp -> PV ----------------
template<int D>
__device__ __forceinline__ void fused_body(
    const float* __restrict__ Wf, const float* __restrict__ XF,
    const float* __restrict__ LTg, const float* __restrict__ QN,
    const float* __restrict__ XN, float* __restrict__ Zout, int qblk){
  extern __shared__ float sm[];
  const int SD = D + 8;                 // stride ≡ 8 (mod 32): LDS.64 conflict-free
  float* Xs0 = sm;
  float* Xs1 = Xs0 + 128*SD;
  float* LT0 = Xs1 + 128*SD;            // Lambda tile, stride 136
  float* LT1 = LT0 + 32*136;
  float* xn0 = LT1 + 32*136;
  float* xn1 = xn0 + 128;
  float* Kt  = xn1 + 128;               // per-warp 32x40 staging
  int tid=threadIdx.x, w=tid>>5, lane=tid&31, gr=lane>>2, p=lane&3;
  int half = w>>2, rbase = (w&3)*32;
  float* Kw = Kt + w*(32*40);
  int q0 = qblk*128;
  const int NF4 = 128*(D/4);

  // ---- prologue: W tile -> A-frags in registers ----
  for(int i=tid;i<NF4;i+=256){
    int r=i/(D/4), c4=i%(D/4);
    cpa16(&Xs0[r*SD+c4*4], &Wf[(size_t)(q0+r)*D + c4*4]);
  }
  cpa_commit(); cpa_wait0(); __syncthreads();
  unsigned wa[2][D/8][4];
  #pragma unroll
  for(int kk=0;kk<D/8;kk++){
    #pragma unroll
    for(int s2=0;s2<2;s2++){
      float2 lo = *(float2*)&Xs0[(rbase+s2*16+gr  )*SD + kk*8+2*p];
      float2 hi = *(float2*)&Xs0[(rbase+s2*16+gr+8)*SD + kk*8+2*p];
      wa[s2][kk][0]=fbits(lo.x); wa[s2][kk][1]=fbits(hi.x);
      wa[s2][kk][2]=fbits(lo.y); wa[s2][kk][3]=fbits(hi.y);
    }
  }
  float qn0=QN[q0+rbase+gr],    qn1=QN[q0+rbase+gr+8];
  float qn2=QN[q0+rbase+gr+16], qn3=QN[q0+rbase+gr+24];
  __syncthreads();

  float z[2][16];
  #pragma unroll
  for(int s2=0;s2<2;s2++)
    #pragma unroll
    for(int i=0;i<16;i++) z[s2][i]=0.f;
  const float CL = 1.1271055e-2f;       // log2(e)/128

  // tile loader
  auto load_tile = [&](float* Xd, float* Ld, float* xd, int xb){
    for(int i=tid;i<NF4;i+=256){
      int r=i/(D/4), c4=i%(D/4);
      cpa16(&Xd[r*SD+c4*4], &XF[(size_t)(xb+r)*D + c4*4]);
    }
    for(int i=tid;i<1024;i+=256){
      int c=i>>5, ch=i&31;
      cpa16(&Ld[c*136+ch*4], &LTg[(size_t)c*NROW + xb + ch*4]);
    }
    if(tid<32) cpa16(&xd[tid*4], &XN[xb+tid*4]);
  };

  load_tile(Xs0, LT0, xn0, 0); cpa_commit();

  for(int t=0;t<64;t++){
    cpa_wait0(); __syncthreads();
    if(t<63){
      if(t&1) load_tile(Xs0, LT0, xn0, (t+1)*128);
      else    load_tile(Xs1, LT1, xn1, (t+1)*128);
      cpa_commit();
    }
    float* X_  = (t&1)? Xs1 : Xs0;
    float* L_  = (t&1)? LT1 : LT0;
    float* xn_ = (t&1)? xn1 : xn0;
    #pragma unroll
    for(int xsi=0; xsi<2; xsi++){
      int xs = half*2 + xsi;
      float s0[16], s1[16];
      #pragma unroll
      for(int i=0;i<16;i++){ s0[i]=0.f; s1[i]=0.f; }
      #pragma unroll
      for(int kk=0;kk<D/8;kk++){
        #pragma unroll
        for(int nt=0;nt<4;nt++){
          float2 b = *(float2*)&X_[(xs*32+nt*8+gr)*SD + kk*8+2*p];
          unsigned b0=fbits(b.x), b1=fbits(b.y);
          mma8(&s0[nt*4], wa[0][kk][0],wa[0][kk][1],wa[0][kk][2],wa[0][kk][3], b0,b1);
          mma8(&s1[nt*4], wa[1][kk][0],wa[1][kk][1],wa[1][kk][2],wa[1][kk][3], b0,b1);
        }
      }
      int pb = (p<2)? 4*p : 4*p-7;      // interleaved store base for cols 2p,2p+1
      #pragma unroll
      for(int nt=0;nt<4;nt++){
        float xnA=xn_[xs*32+nt*8+2*p], xnB=xn_[xs*32+nt*8+2*p+1];
        Kw[(gr   )*40+nt*8+pb  ]=tf2f(ex2f(fminf(2.f*s0[nt*4+0]-qn0-xnA,0.f)*CL));
        Kw[(gr   )*40+nt*8+pb+2]=tf2f(ex2f(fminf(2.f*s0[nt*4+1]-qn0-xnB,0.f)*CL));
        Kw[(gr+ 8)*40+nt*8+pb  ]=tf2f(ex2f(fminf(2.f*s0[nt*4+2]-qn1-xnA,0.f)*CL));
        Kw[(gr+ 8)*40+nt*8+pb+2]=tf2f(ex2f(fminf(2.f*s0[nt*4+3]-qn1-xnB,0.f)*CL));
        Kw[(gr+16)*40+nt*8+pb  ]=tf2f(ex2f(fminf(2.f*s1[nt*4+0]-qn2-xnA,0.f)*CL));
        Kw[(gr+16)*40+nt*8+pb+2]=tf2f(ex2f(fminf(2.f*s1[nt*4+1]-qn2-xnB,0.f)*CL));
        Kw[(gr+24)*40+nt*8+pb  ]=tf2f(ex2f(fminf(2.f*s1[nt*4+2]-qn3-xnA,0.f)*CL));
        Kw[(gr+24)*40+nt*8+pb+2]=tf2f(ex2f(fminf(2.f*s1[nt*4+3]-qn3-xnB,0.f)*CL));
      }
      __syncwarp();
      #pragma unroll
      for(int kc=0;kc<4;kc++){
        float2 A0l=*(float2*)&Kw[(gr   )*40+kc*8+2*p];
        float2 A0h=*(float2*)&Kw[(gr+ 8)*40+kc*8+2*p];
        float2 A1l=*(float2*)&Kw[(gr+16)*40+kc*8+2*p];
        float2 A1h=*(float2*)&Kw[(gr+24)*40+kc*8+2*p];
        #pragma unroll
        for(int nt=0;nt<4;nt++){
          float2 b=*(float2*)&L_[(nt*8+gr)*136 + xs*32 + kc*8+2*p];
          unsigned b0=fbits(b.x), b1=fbits(b.y);
          mma8(&z[0][nt*4], fbits(A0l.x),fbits(A0h.x),fbits(A0l.y),fbits(A0h.y), b0,b1);
          mma8(&z[1][nt*4], fbits(A1l.x),fbits(A1h.x),fbits(A1l.y),fbits(A1h.y), b0,b1);
        }
      }
      __syncwarp();
    }
  }

  // ---- cross-half z reduction ----
  __syncthreads();
  float* Zr = LT0;                      // reuse (128 x 34)
  if(half==0){
    #pragma unroll
    for(int s2=0;s2<2;s2++)
      #pragma unroll
      for(int nt=0;nt<4;nt++){
        *(float2*)&Zr[(rbase+s2*16+gr  )*34 + nt*8+2*p] = make_float2(z[s2][nt*4+0], z[s2][nt*4+1]);
        *(float2*)&Zr[(rbase+s2*16+gr+8)*34 + nt*8+2*p] = make_float2(z[s2][nt*4+2], z[s2][nt*4+3]);
      }
  }
  __syncthreads();
  if(half==1){
    #pragma unroll
    for(int s2=0;s2<2;s2++)
      #pragma unroll
      for(int nt=0;nt<4;nt++){
        float2 a=*(float2*)&Zr[(rbase+s2*16+gr  )*34 + nt*8+2*p];
        float2 b=*(float2*)&Zr[(rbase+s2*16+gr+8)*34 + nt*8+2*p];
        *(float2*)&Zout[(size_t)(q0+rbase+s2*16+gr  )*32 + nt*8+2*p] =
            make_float2(a.x+z[s2][nt*4+0], a.y+z[s2][nt*4+1]);
        *(float2*)&Zout[(size_t)(q0+rbase+s2*16+gr+8)*32 + nt*8+2*p] =
            make_float2(b.x+z[s2][nt*4+2], b.y+z[s2][nt*4+3]);
      }
  }
}

__global__ __launch_bounds__(256,1) void fused_kernel(){
  if(blockIdx.y==0) fused_body<64>(g_Wm,g_XFm,g_LTm,g_QNm,g_XNm,g_Zm,blockIdx.x);
  else              fused_body<96>(g_Wv,g_XFv,g_LTv,g_QNv,g_XNv,g_Zv,blockIdx.x);
}

// ---------------- 4) finalize ----------------
__global__ __launch_bounds__(256) void final_kernel(
    const float* __restrict__ y_mean, const float* __restrict__ y_var,
    float* __restrict__ out){
  int i = blockIdx.x*256 + threadIdx.x;
  float4 a=*(const float4*)&y_mean[i*4];
  float4 b=*(const float4*)&y_var [i*4];
  float4 zm=*(const float4*)&g_Zm[i*4];
  float4 zv=*(const float4*)&g_Zv[i*4];
  float4 o;
  o.x=a.x+b.x+zm.x+zv.x; o.y=a.y+b.y+zm.y+zv.y;
  o.z=a.z+b.z+zm.z+zv.z; o.w=a.w+b.w+zm.w+zv.w;
  *(float4*)&out[i*4]=o;
}

extern "C" void kernel_launch(void* const* d_in, const int* in_sizes, int n_in,
                              void* d_out, int out_size){
  const float* x_mu   = (const float*)d_in[0];
  const float* y_eta  = (const float*)d_in[1];
  const float* y_mean = (const float*)d_in[2];
  const float* y_var  = (const float*)d_in[3];
  const float* X_mean = (const float*)d_in[4];
  const float* X_var  = (const float*)d_in[5];
  const float* Z_mean = (const float*)d_in[6];
  const float* Z_var  = (const float*)d_in[7];
  const float* kMinv  = (const float*)d_in[8];
  const float* kVinv  = (const float*)d_in[9];
  float* out = (float*)d_out;

  prep_kernel<<<NROW/8, 256>>>(x_mu, y_eta, y_mean, y_var, X_mean, X_var);
  lambda_kernel<<<dim3(NROW/32,4,2), 64>>>(kMinv, kVinv, Z_mean, Z_var);
  reduce_kernel<<<dim3(256,2), 256>>>();
  const int FSM = (2*128*104 + 2*32*136 + 2*128 + 8*32*40)*4;   // 183296 B
  cudaFuncSetAttribute(fused_kernel, cudaFuncAttributeMaxDynamicSharedMemorySize, FSM);
  fused_kernel<<<dim3(64,2), 256, FSM>>>();
  final_kernel<<<NROW*32/4/256, 256>>>(y_mean, y_var, out);
}

// round 5
// speedup vs baseline: 1.8732x; 1.0557x over previous
#include <cuda_runtime.h>
#include <cstdint>

#define NROW 8192

// ---------------- scratch ----------------
__device__ float g_Wm [NROW*64];         // pair-interleaved cols, tf32
__device__ float g_Wv [NROW*96];
__device__ float g_XFm[NROW*64];
__device__ float g_XFv[NROW*96];
__device__ float g_Lp [2][4][NROW*32];   // lambda partials (fp32)
__device__ float g_LTm[32*NROW];         // Lambda^T, col-interleaved, tf32
__device__ float g_LTv[32*NROW];
__device__ float g_QNm[NROW];
__device__ float g_QNv[NROW];
__device__ float g_XNm[NROW];
__device__ float g_XNv[NROW];
__device__ float g_Zm [NROW*32];
__device__ float g_Zv [NROW*32];

__device__ __forceinline__ unsigned f2tf(float x){
  unsigned r; asm("cvt.rna.tf32.f32 %0, %1;" : "=r"(r) : "f"(x)); return r;
}
__device__ __forceinline__ float tf2f(float x){ return __uint_as_float(f2tf(x)); }
__device__ __forceinline__ float ex2f(float x){
  float r; asm("ex2.approx.f32 %0, %1;" : "=f"(r) : "f"(x)); return r;
}
__device__ __forceinline__ unsigned fbits(float x){ return __float_as_uint(x); }
__device__ __forceinline__ void mma8(float* c, unsigned a0,unsigned a1,unsigned a2,unsigned a3,
                                     unsigned b0,unsigned b1){
  asm volatile("mma.sync.aligned.m16n8k8.row.col.f32.tf32.tf32.f32 "
               "{%0,%1,%2,%3},{%4,%5,%6,%7},{%8,%9},{%0,%1,%2,%3};\n"
               : "+f"(c[0]), "+f"(c[1]), "+f"(c[2]), "+f"(c[3])
               : "r"(a0), "r"(a1), "r"(a2), "r"(a3), "r"(b0), "r"(b1));
}
__device__ __forceinline__ void cpa16(void* dst, const void* src){
  unsigned d = (unsigned)__cvta_generic_to_shared(dst);
  asm volatile("cp.async.cg.shared.global [%0], [%1], 16;\n" :: "r"(d), "l"(src));
}
__device__ __forceinline__ void cpa_commit(){ asm volatile("cp.async.commit_group;\n"); }
__device__ __forceinline__ void cpa_wait0(){ asm volatile("cp.async.wait_group 0;\n"); }
__device__ __forceinline__ void cpa_wait1(){ asm volatile("cp.async.wait_group 1;\n"); }

// pair-interleave within 8-groups: orig offset j -> 2*(j&3) + ((j&4)>>2)
__device__ __forceinline__ int ilv(int j){ return (j & ~7) + 2*(j&3) + ((j&4)>>2); }

// ---------------- 1) prep ----------------
__global__ __launch_bounds__(256) void prep_kernel(
    const float* __restrict__ x_mu, const float* __restrict__ y_eta,
    const float* __restrict__ y_mean, const float* __restrict__ y_var,
    const float* __restrict__ X_mean, const float* __restrict__ X_var){
  int row  = blockIdx.x*8 + (threadIdx.x>>5);
  int lane = threadIdx.x & 31;
  int il   = ilv(lane);
  float xm = x_mu [row*32+lane];
  float s  = y_mean[row*32+lane] + y_var[row*32+lane];
  float fe = 0.01f * y_eta[(NROW-1-row)*32+lane];
  g_Wm[row*64+il]    = tf2f(xm);
  g_Wm[row*64+32+il] = tf2f(s);
  g_Wv[row*96+il]    = tf2f(xm);
  g_Wv[row*96+32+il] = tf2f(fe);
  g_Wv[row*96+64+il] = tf2f(s);
  float qm = xm*xm + s*s;
  float qv = qm + fe*fe;
  float a  = X_mean[row*64+lane], bm = X_mean[row*64+32+lane];
  g_XFm[row*64+il]    = tf2f(a);
  g_XFm[row*64+32+il] = tf2f(bm);
  float nm = a*a + bm*bm;
  float c0 = X_var[row*96+lane], c1 = X_var[row*96+32+lane], c2 = X_var[row*96+64+lane];
  g_XFv[row*96+il]    = tf2f(c0);
  g_XFv[row*96+32+il] = tf2f(c1);
  g_XFv[row*96+64+il] = tf2f(c2);
  float nv = c0*c0 + c1*c1 + c2*c2;
  #pragma unroll
  for(int o=16;o;o>>=1){
    qm += __shfl_xor_sync(0xffffffffu,qm,o);
    qv += __shfl_xor_sync(0xffffffffu,qv,o);
    nm += __shfl_xor_sync(0xffffffffu,nm,o);
    nv += __shfl_xor_sync(0xffffffffu,nv,o);
  }
  if(lane==0){ g_QNm[row]=qm; g_QNv[row]=qv; g_XNm[row]=nm; g_XNv[row]=nv; }
}

// ---------------- 2) Lambda partials (K-split x4, cp.async 2-stage) ----------------
__global__ __launch_bounds__(128) void lambda_kernel(
    const float* __restrict__ Am, const float* __restrict__ Av,
    const float* __restrict__ Zm, const float* __restrict__ Zv){
  int path = blockIdx.z, ks = blockIdx.y;
  const float* A = path ? Av : Am;
  const float* Z = path ? Zv : Zm;
  float* L = &g_Lp[path][ks][0];
  __shared__ float As[2][64*36];
  __shared__ float Zs[2][32*40];
  int tid=threadIdx.x, w=tid>>5, lane=tid&31, gr=lane>>2, p=lane&3;
  int rb = blockIdx.x*64, kbase = ks*2048;

  auto load = [&](int st, int k0){
    #pragma unroll
    for(int i=0;i<4;i++){
      int idx=tid+128*i; int r=idx>>3, c4=idx&7;
      cpa16(&As[st][r*36+c4*4], &A[(size_t)(rb+r)*NROW + k0 + c4*4]);
    }
    #pragma unroll
    for(int i=0;i<2;i++){
      int idx=tid+128*i; int r=idx>>3, c4=idx&7;
      cpa16(&Zs[st][r*40+c4*4], &Z[(size_t)(k0+r)*32 + c4*4]);
    }
  };

  load(0, kbase); cpa_commit();
  float acc[16];
  #pragma unroll
  for(int i=0;i<16;i++) acc[i]=0.f;

  for(int kt=0;kt<64;kt++){
    if(kt<63){ load((kt+1)&1, kbase+(kt+1)*32); cpa_commit(); cpa_wait1(); }
    else cpa_wait0();
    __syncthreads();
    const float* Ax = As[kt&1];
    const float* Zx = Zs[kt&1];
    #pragma unroll
    for(int kc=0;kc<4;kc++){
      unsigned a0=f2tf(Ax[(w*16+gr  )*36 + kc*8+p  ]);
      unsigned a1=f2tf(Ax[(w*16+gr+8)*36 + kc*8+p  ]);
      unsigned a2=f2tf(Ax[(w*16+gr  )*36 + kc*8+p+4]);
      unsigned a3=f2tf(Ax[(w*16+gr+8)*36 + kc*8+p+4]);
      #pragma unroll
      for(int nt=0;nt<4;nt++){
        unsigned b0=f2tf(Zx[(kc*8+p  )*40 + nt*8+gr]);
        unsigned b1=f2tf(Zx[(kc*8+p+4)*40 + nt*8+gr]);
        mma8(&acc[nt*4], a0,a1,a2,a3, b0,b1);
      }
    }
    __syncthreads();
  }
  int q = rb + w*16 + gr;
  #pragma unroll
  for(int nt=0;nt<4;nt++){
    L[ q   *32 + nt*8 + 2*p  ] = acc[nt*4+0];
    L[ q   *32 + nt*8 + 2*p+1] = acc[nt*4+1];
    L[(q+8)*32 + nt*8 + 2*p  ] = acc[nt*4+2];
    L[(q+8)*32 + nt*8 + 2*p+1] = acc[nt*4+3];
  }
}

// ---------------- 2b) reduce partials -> Lambda^T interleaved ----------------
__global__ __launch_bounds__(256) void reduce_kernel(){
  int path = blockIdx.y;
  int idx  = blockIdx.x*256 + threadIdx.x;
  int r = idx>>3, c4 = idx&7;
  float4 s0 = *(const float4*)&g_Lp[path][0][idx*4];
  float4 s1 = *(const float4*)&g_Lp[path][1][idx*4];
  float4 s2 = *(const float4*)&g_Lp[path][2][idx*4];
  float4 s3 = *(const float4*)&g_Lp[path][3][idx*4];
  float vx = s0.x+s1.x+s2.x+s3.x;
  float vy = s0.y+s1.y+s2.y+s3.y;
  float vz = s0.z+s1.z+s2.z+s3.z;
  float vw = s0.w+s1.w+s2.w+s3.w;
  int pos = ilv(r);
  float* LT = path ? g_LTv : g_LTm;
  LT[(c4*4+0)*NROW + pos] = tf2f(vx);
  LT[(c4*4+1)*NROW + pos] = tf2f(vy);
  LT[(c4*4+2)*NROW + pos] = tf2f(vz);
  LT[(c4*4+3)*NROW + pos] = tf2f(vw);
}

// ---------------- 3) fused scores -> exp -> PV (16 warps, M=16/warp) ----------------
template<int D>
__device__ __forceinline__ void fused_body(
    const float* __restrict__ Wf, const float* __restrict__ XF,
    const float* __restrict__ LTg, const float* __restrict__ QN,
    const float* __restrict__ XN, float* __restrict__ Zout, int qblk){
  extern __shared__ float sm[];
  const int SD = D + 8;
  float* Xs0 = sm;
  float* Xs1 = Xs0 + 128*SD;
  float* LT0 = Xs1 + 128*SD;            // Lambda tile, 32 x 136
  float* LT1 = LT0 + 32*136;
  float* xn0 = LT1 + 32*136;
  float* xn1 = xn0 + 128;
  float* Kt  = xn1 + 128;               // 16 warps x (16x40)
  int tid=threadIdx.x, w=tid>>5, lane=tid&31, gr=lane>>2, p=lane&3;
  int half = w>>3, rbase = (w&7)*16;
  float* Kw = Kt + w*(16*40);
  int q0 = qblk*128;
  const int NF4 = 128*(D/4);

  for(int i=tid;i<NF4;i+=512){
    int r=i/(D/4), c4=i%(D/4);
    cpa16(&Xs0[r*SD+c4*4], &Wf[(size_t)(q0+r)*D + c4*4]);
  }
  cpa_commit(); cpa_wait0(); __syncthreads();
  unsigned wa[D/8][4];
  #pragma unroll
  for(int kk=0;kk<D/8;kk++){
    float2 lo = *(float2*)&Xs0[(rbase+gr  )*SD + kk*8+2*p];
    float2 hi = *(float2*)&Xs0[(rbase+gr+8)*SD + kk*8+2*p];
    wa[kk][0]=fbits(lo.x); wa[kk][1]=fbits(hi.x);
    wa[kk][2]=fbits(lo.y); wa[kk][3]=fbits(hi.y);
  }
  float qn0=QN[q0+rbase+gr], qn1=QN[q0+rbase+gr+8];
  __syncthreads();

  float z[16];
  #pragma unroll
  for(int i=0;i<16;i++) z[i]=0.f;
  const float CL = 1.1271055e-2f;       // log2(e)/128

  auto load_tile = [&](float* Xd, float* Ld, float* xd, int xb){
    for(int i=tid;i<NF4;i+=512){
      int r=i/(D/4), c4=i%(D/4);
      cpa16(&Xd[r*SD+c4*4], &XF[(size_t)(xb+r)*D + c4*4]);
    }
    for(int i=tid;i<1024;i+=512){
      int c=i>>5, ch=i&31;
      cpa16(&Ld[c*136+ch*4], &LTg[(size_t)c*NROW + xb + ch*4]);
    }
    if(tid<32) cpa16(&xd[tid*4], &XN[xb+tid*4]);
  };

  load_tile(Xs0, LT0, xn0, 0); cpa_commit();

  for(int t=0;t<64;t++){
    cpa_wait0(); __syncthreads();
    if(t<63){
      if(t&1) load_tile(Xs0, LT0, xn0, (t+1)*128);
      else    load_tile(Xs1, LT1, xn1, (t+1)*128);
      cpa_commit();
    }
    float* X_  = (t&1)? Xs1 : Xs0;
    float* L_  = (t&1)? LT1 : LT0;
    float* xn_ = (t&1)? xn1 : xn0;
    #pragma unroll
    for(int xsi=0; xsi<2; xsi++){
      int xs = half*2 + xsi;
      float s[16];
      #pragma unroll
      for(int i=0;i<16;i++) s[i]=0.f;
      #pragma unroll
      for(int kk=0;kk<D/8;kk++){
        #pragma unroll
        for(int nt=0;nt<4;nt++){
          float2 b = *(float2*)&X_[(xs*32+nt*8+gr)*SD + kk*8+2*p];
          mma8(&s[nt*4], wa[kk][0],wa[kk][1],wa[kk][2],wa[kk][3], fbits(b.x),fbits(b.y));
        }
      }
      int pb = (p<2)? 4*p : 4*p-7;      // interleaved store base for cols 2p,2p+1
      #pragma unroll
      for(int nt=0;nt<4;nt++){
        float xnA=xn_[xs*32+nt*8+2*p], xnB=xn_[xs*32+nt*8+2*p+1];
        Kw[(gr  )*40+nt*8+pb  ]=tf2f(ex2f(fminf(2.f*s[nt*4+0]-qn0-xnA,0.f)*CL));
        Kw[(gr  )*40+nt*8+pb+2]=tf2f(ex2f(fminf(2.f*s[nt*4+1]-qn0-xnB,0.f)*CL));
        Kw[(gr+8)*40+nt*8+pb  ]=tf2f(ex2f(fminf(2.f*s[nt*4+2]-qn1-xnA,0.f)*CL));
        Kw[(gr+8)*40+nt*8+pb+2]=tf2f(ex2f(fminf(2.f*s[nt*4+3]-qn1-xnB,0.f)*CL));
      }
      __syncwarp();
      #pragma unroll
      for(int kc=0;kc<4;kc++){
        float2 Al=*(float2*)&Kw[(gr  )*40+kc*8+2*p];
        float2 Ah=*(float2*)&Kw[(gr+8)*40+kc*8+2*p];
        #pragma unroll
        for(int nt=0;nt<4;nt++){
          float2 b=*(float2*)&L_[(nt*8+gr)*136 + xs*32 + kc*8+2*p];
          mma8(&z[nt*4], fbits(Al.x),fbits(Ah.x),fbits(Al.y),fbits(Ah.y),
               fbits(b.x),fbits(b.y));
        }
      }
      __syncwarp();
    }
  }

  // ---- cross-half z reduction ----
  __syncthreads();
  float* Zr = LT0;                      // reuse (128 x 34 <= 32*136*... fits)
  if(half==0){
    #pragma unroll
    for(int nt=0;nt<4;nt++){
      *(float2*)&Zr[(rbase+gr  )*34 + nt*8+2*p] = make_float2(z[nt*4+0], z[nt*4+1]);
      *(float2*)&Zr[(rbase+gr+8)*34 + nt*8+2*p] = make_float2(z[nt*4+2], z[nt*4+3]);
    }
  }
  __syncthreads();
  if(half==1){
    #pragma unroll
    for(int nt=0;nt<4;nt++){
      float2 a=*(float2*)&Zr[(rbase+gr  )*34 + nt*8+2*p];
      float2 b=*(float2*)&Zr[(rbase+gr+8)*34 + nt*8+2*p];
      *(float2*)&Zout[(size_t)(q0+rbase+gr  )*32 + nt*8+2*p] =
          make_float2(a.x+z[nt*4+0], a.y+z[nt*4+1]);
      *(float2*)&Zout[(size_t)(q0+rbase+gr+8)*32 + nt*8+2*p] =
          make_float2(b.x+z[nt*4+2], b.y+z[nt*4+3]);
    }
  }
}

__global__ __launch_bounds__(512,1) void fused_kernel(){
  if(blockIdx.y==0) fused_body<64>(g_Wm,g_XFm,g_LTm,g_QNm,g_XNm,g_Zm,blockIdx.x);
  else              fused_body<96>(g_Wv,g_XFv,g_LTv,g_QNv,g_XNv,g_Zv,blockIdx.x);
}

// ---------------- 4) finalize ----------------
__global__ __launch_bounds__(256) void final_kernel(
    const float* __restrict__ y_mean, const float* __restrict__ y_var,
    float* __restrict__ out){
  int i = blockIdx.x*256 + threadIdx.x;
  float4 a=*(const float4*)&y_mean[i*4];
  float4 b=*(const float4*)&y_var [i*4];
  float4 zm=*(const float4*)&g_Zm[i*4];
  float4 zv=*(const float4*)&g_Zv[i*4];
  float4 o;
  o.x=a.x+b.x+zm.x+zv.x; o.y=a.y+b.y+zm.y+zv.y;
  o.z=a.z+b.z+zm.z+zv.z; o.w=a.w+b.w+zm.w+zv.w;
  *(float4*)&out[i*4]=o;
}

extern "C" void kernel_launch(void* const* d_in, const int* in_sizes, int n_in,
                              void* d_out, int out_size){
  const float* x_mu   = (const float*)d_in[0];
  const float* y_eta  = (const float*)d_in[1];
  const float* y_mean = (const float*)d_in[2];
  const float* y_var  = (const float*)d_in[3];
  const float* X_mean = (const float*)d_in[4];
  const float* X_var  = (const float*)d_in[5];
  const float* Z_mean = (const float*)d_in[6];
  const float* Z_var  = (const float*)d_in[7];
  const float* kMinv  = (const float*)d_in[8];
  const float* kVinv  = (const float*)d_in[9];
  float* out = (float*)d_out;

  prep_kernel<<<NROW/8, 256>>>(x_mu, y_eta, y_mean, y_var, X_mean, X_var);
  lambda_kernel<<<dim3(NROW/64,4,2), 128>>>(kMinv, kVinv, Z_mean, Z_var);
  reduce_kernel<<<dim3(256,2), 256>>>();
  const int FSM = (2*128*104 + 2*32*136 + 2*128 + 16*16*40)*4;   // 183296 B
  cudaFuncSetAttribute(fused_kernel, cudaFuncAttributeMaxDynamicSharedMemorySize, FSM);
  fused_kernel<<<dim3(64,2), 512, FSM>>>();
  final_kernel<<<NROW*32/4/256, 256>>>(y_mean, y_var, out);
}